// round 15
// baseline (speedup 1.0000x reference)
#include <cuda_runtime.h>
#include <stdint.h>

#define FULLMASK 0xFFFFFFFFu

static constexpr int Bc = 4;
static constexpr int Nc = 8192;
static constexpr int Pc = 2048;
static constexpr int Sc = 32;

// packed xyz scratch (512 KB) — __device__ global, no allocation
__device__ float4 g_xyz4[Bc * Nc];

// --- precise (non-contracted) helpers: mimic XLA's separate mul/add/div ops ---
__device__ __forceinline__ float d3(float ax, float ay, float az,
                                    float bx, float by, float bz) {
    // ((a0*b0 + a1*b1) + a2*b2), all round-to-nearest, no FMA contraction
    return __fadd_rn(__fadd_rn(__fmul_rn(ax, bx), __fmul_rn(ay, by)),
                     __fmul_rn(az, bz));
}

__global__ void pack_xyz_kernel(const float* __restrict__ xyz) {
    int i = blockIdx.x * blockDim.x + threadIdx.x;
    if (i < Bc * Nc) {
        float x = xyz[3 * i + 0];
        float y = xyz[3 * i + 1];
        float z = xyz[3 * i + 2];
        g_xyz4[i] = make_float4(x, y, z, 0.0f);
    }
}

__device__ __forceinline__ uint32_t rotl32(uint32_t x, int r) {
    return (x << r) | (x >> (32 - r));
}

// Bit-exact replica of jax.random.uniform(jax.random.key(42), (B,1,P,32)) with
// the PARTITIONABLE threefry implementation (default in modern JAX):
//   per element, 64-bit counter = row-major flat index f;
//   threefry2x32(key=[0,42], x0 = hi32(f) = 0, x1 = lo32(f) = f);
//   32-bit draw = x0_final ^ x1_final;
//   u = bitcast((bits >> 9) | 0x3f800000) - 1;  angle = (u - 0.5) * 2*pi.
__device__ __forceinline__ float rand_angle(uint32_t f) {
    const uint32_t k0 = 0u, k1 = 42u;
    const uint32_t k2 = 0x1BD11BDAu ^ k0 ^ k1;
    uint32_t x0 = 0u + k0;   // hi half of the 64-bit counter (always 0 here)
    uint32_t x1 = f + k1;    // lo half
#define R4(a, b, c, d)                         \
    x0 += x1; x1 = rotl32(x1, a); x1 ^= x0;    \
    x0 += x1; x1 = rotl32(x1, b); x1 ^= x0;    \
    x0 += x1; x1 = rotl32(x1, c); x1 ^= x0;    \
    x0 += x1; x1 = rotl32(x1, d); x1 ^= x0;
    R4(13, 15, 26, 6)   x0 += k1; x1 += k2 + 1u;
    R4(17, 29, 16, 24)  x0 += k2; x1 += k0 + 2u;
    R4(13, 15, 26, 6)   x0 += k0; x1 += k1 + 3u;
    R4(17, 29, 16, 24)  x0 += k1; x1 += k2 + 4u;
    R4(13, 15, 26, 6)   x0 += k2; x1 += k0 + 5u;
#undef R4
    uint32_t bits = x0 ^ x1;   // 32-bit fold used by partitionable threefry
    float u = __fsub_rn(__uint_as_float((bits >> 9) | 0x3F800000u), 1.0f);
    return __fmul_rn(__fsub_rn(u, 0.5f), 6.28318530717958647692f);
}

// One warp per query point.
__global__ void __launch_bounds__(256, 4)
qgq_kernel(const float* __restrict__ new_xyz,   // (B, P, 3)
           float* __restrict__ out)             // (B, 34, P, 32)
{
    const int wglobal = (blockIdx.x * blockDim.x + threadIdx.x) >> 5;
    const int lane    = threadIdx.x & 31;
    if (wglobal >= Bc * Pc) return;
    const int b = wglobal / Pc;
    const int p = wglobal % Pc;

    __shared__ int s_idx[8][32];
    int* slots = s_idx[threadIdx.x >> 5];

    const float* c3 = new_xyz + (size_t)(b * Pc + p) * 3;
    const float cx = c3[0], cy = c3[1], cz = c3[2];
    const float4* pts = g_xyz4 + (size_t)b * Nc;

    // ---- ball query: first 32 ascending-index hits, early exit ----
    int cnt = 0;
    const unsigned lt_mask = (1u << lane) - 1u;
    for (int base = 0; base < Nc; base += 32) {
        float4 q = pts[base + lane];
        float dx = __fsub_rn(cx, q.x);
        float dy = __fsub_rn(cy, q.y);
        float dz = __fsub_rn(cz, q.z);
        float d2 = d3(dx, dy, dz, dx, dy, dz);
        bool hit = d2 < 0.04f;                 // RADIUS^2 in f32
        unsigned m = __ballot_sync(FULLMASK, hit);
        if (hit) {
            int slot = cnt + __popc(m & lt_mask);
            if (slot < 32) slots[slot] = base + lane;
        }
        cnt += __popc(m);
        if (cnt >= 32) break;
    }
    __syncwarp();
    if (lane >= cnt) slots[lane] = slots[0];   // pad with first hit (cnt >= 1 always)
    __syncwarp();
    const int myn = slots[lane];

    // ---- relative vector ----
    float4 q4 = pts[myn];
    float vx = __fsub_rn(q4.x, cx);
    float vy = __fsub_rn(q4.y, cy);
    float vz = __fsub_rn(q4.z, cz);

    // ---- p1 = normalize(center); p2 = normalize(p1) (double-normalized in ref) ----
    const float eps = 1e-6f;
    float cn  = sqrtf(d3(cx, cy, cz, cx, cy, cz));
    float cd  = __fadd_rn(cn, eps);
    float p1x = __fdiv_rn(cx, cd), p1y = __fdiv_rn(cy, cd), p1z = __fdiv_rn(cz, cd);

    float n1  = sqrtf(d3(p1x, p1y, p1z, p1x, p1y, p1z));
    float n1d = __fadd_rn(n1, eps);
    float p2x = __fdiv_rn(p1x, n1d), p2y = __fdiv_rn(p1y, n1d), p2z = __fdiv_rn(p1z, n1d);

    // ---- ref = _project_one(p1) ----
    bool colin = fabsf(p2x) > 0.999f;
    float rx, ry, rz;
    if (colin) {
        rx = -__fmul_rn(p2y, p2x);
        ry = __fsub_rn(1.0f, __fmul_rn(p2y, p2y));
        rz = -__fmul_rn(p2y, p2z);
    } else {
        rx = __fsub_rn(1.0f, __fmul_rn(p2x, p2x));
        ry = -__fmul_rn(p2x, p2y);
        rz = -__fmul_rn(p2x, p2z);
    }
    float rn_  = sqrtf(d3(rx, ry, rz, rx, ry, rz));
    float rnd_ = __fadd_rn(rn_, eps);
    float rfx = __fdiv_rn(rx, rnd_), rfy = __fdiv_rn(ry, rnd_), rfz = __fdiv_rn(rz, rnd_);

    // ---- projection onto plane perpendicular to p1 ----
    float dotpv = d3(p1x, p1y, p1z, vx, vy, vz);
    float ddx = __fsub_rn(vx, __fmul_rn(dotpv, p1x));
    float ddy = __fsub_rn(vy, __fmul_rn(dotpv, p1y));
    float ddz = __fsub_rn(vz, __fmul_rn(dotpv, p1z));
    float pn  = sqrtf(d3(ddx, ddy, ddz, ddx, ddy, ddz));
    float pnd = __fadd_rn(pn, eps);
    float pjx = __fdiv_rn(ddx, pnd), pjy = __fdiv_rn(ddy, pnd), pjz = __fdiv_rn(ddz, pnd);

    // ---- angle = atan2(triple(ref,proj,p1), ref.proj), random if degenerate ----
    float cxp = __fsub_rn(__fmul_rn(rfy, pjz), __fmul_rn(rfz, pjy));
    float cyp = __fsub_rn(__fmul_rn(rfz, pjx), __fmul_rn(rfx, pjz));
    float czp = __fsub_rn(__fmul_rn(rfx, pjy), __fmul_rn(rfy, pjx));
    float sinus   = d3(cxp, cyp, czp, p1x, p1y, p1z);
    float cosinus = d3(rfx, rfy, rfz, pjx, pjy, pjz);
    float pn2 = d3(pjx, pjy, pjz, pjx, pjy, pjz);

    float angle;
    if (pn2 < 1e-12f) {
        uint32_t flat = (uint32_t)((b * Pc + p) * Sc + lane);
        angle = rand_angle(flat);
    } else {
        angle = atan2f(sinus, cosinus);   // XLA atan2 lowers to __nv_atan2f: identical
    }

    // ---- stable argsort via warp bitonic on (ordered-float(angle), lane) ----
    unsigned ab = __float_as_uint(angle);
    ab = (ab & 0x80000000u) ? ~ab : (ab | 0x80000000u);
    unsigned long long key = ((unsigned long long)ab << 32) | (unsigned)lane;
    #pragma unroll
    for (int k = 2; k <= 32; k <<= 1) {
        #pragma unroll
        for (int j = k >> 1; j > 0; j >>= 1) {
            unsigned long long o = __shfl_xor_sync(FULLMASK, key, j);
            bool up      = ((lane & k) == 0);
            bool lower   = ((lane & j) == 0);
            bool takeMin = (up == lower);
            key = ((key < o) == takeMin) ? key : o;
        }
    }
    int src = (int)(key & 31u);
    float svx = __shfl_sync(FULLMASK, vx, src);
    float svy = __shfl_sync(FULLMASK, vy, src);
    float svz = __shfl_sync(FULLMASK, vz, src);

    // ---- invariance features ----
    float ss   = d3(svx, svy, svz, svx, svy, svz);
    float n2   = sqrtf(__fadd_rn(ss, 1e-12f));
    float cang = __fdiv_rn(d3(p1x, p1y, p1z, svx, svy, svz), n2);
    cang = fminf(fmaxf(cang, -0.999999f), 0.999999f);
    float iang = acosf(cang);

    // ---- quaternion ----
    float dist = sqrtf(ss);
    float od   = __fadd_rn(dist, eps);
    float ox = __fdiv_rn(svx, od), oy = __fdiv_rn(svy, od), oz = __fdiv_rn(svz, od);
    float theta = __fmul_rn(__fdiv_rn(dist, 0.2f), 1.57079632679489661923f);
    float qw = cosf(theta);
    float sn = sinf(theta);
    float qx = __fmul_rn(sn, ox);
    float qy = __fmul_rn(sn, oy);
    float qz = __fmul_rn(sn, oz);

    // ---- write output: out[b][ch][p][s], ch: 0=norm,1=angle, 2+qi*8+m = roll(q_qi,-m) ----
    float* ob = out + (((size_t)b * 34) * Pc + p) * Sc + lane;
    const size_t chs = (size_t)Pc * Sc;
    ob[0 * chs] = n2;
    ob[1 * chs] = iang;

    float qv0 = qw, qv1 = qx, qv2 = qy, qv3 = qz;
    #pragma unroll
    for (int m = 0; m < 8; m++) {
        int srcl = (lane + m) & 31;
        float r0 = __shfl_sync(FULLMASK, qv0, srcl);
        float r1 = __shfl_sync(FULLMASK, qv1, srcl);
        float r2 = __shfl_sync(FULLMASK, qv2, srcl);
        float r3 = __shfl_sync(FULLMASK, qv3, srcl);
        ob[(size_t)(2 + 0 * 8 + m) * chs] = r0;
        ob[(size_t)(2 + 1 * 8 + m) * chs] = r1;
        ob[(size_t)(2 + 2 * 8 + m) * chs] = r2;
        ob[(size_t)(2 + 3 * 8 + m) * chs] = r3;
    }
}

extern "C" void kernel_launch(void* const* d_in, const int* in_sizes, int n_in,
                              void* d_out, int out_size) {
    const float* xyz     = (const float*)d_in[0];   // (4, 8192, 3)
    const float* new_xyz = (const float*)d_in[1];   // (4, 2048, 3)
    // d_in[2] = fps_idx: unused (its column is dropped by grouped[..., 1:])
    float* out = (float*)d_out;                     // (4, 34, 2048, 32)

    pack_xyz_kernel<<<(Bc * Nc + 255) / 256, 256>>>(xyz);

    // 8192 query points, one warp each: 1024 blocks x 256 threads
    qgq_kernel<<<(Bc * Pc * 32) / 256, 256>>>(new_xyz, out);
}

// round 16
// speedup vs baseline: 1.1760x; 1.1760x over previous
#include <cuda_runtime.h>
#include <stdint.h>

#define FULLMASK 0xFFFFFFFFu

static constexpr int Bc = 4;
static constexpr int Nc = 8192;
static constexpr int Pc = 2048;
static constexpr int Sc = 32;

// packed xyz scratch (512 KB) — __device__ global, no allocation
__device__ float4 g_xyz4[Bc * Nc];

// --- precise (non-contracted) helpers: mimic XLA's separate mul/add/div ops ---
__device__ __forceinline__ float d3(float ax, float ay, float az,
                                    float bx, float by, float bz) {
    // ((a0*b0 + a1*b1) + a2*b2), all round-to-nearest, no FMA contraction
    return __fadd_rn(__fadd_rn(__fmul_rn(ax, bx), __fmul_rn(ay, by)),
                     __fmul_rn(az, bz));
}

__global__ void pack_xyz_kernel(const float* __restrict__ xyz) {
    int i = blockIdx.x * blockDim.x + threadIdx.x;
    if (i < Bc * Nc) {
        float x = xyz[3 * i + 0];
        float y = xyz[3 * i + 1];
        float z = xyz[3 * i + 2];
        g_xyz4[i] = make_float4(x, y, z, 0.0f);
    }
}

__device__ __forceinline__ uint32_t rotl32(uint32_t x, int r) {
    return (x << r) | (x >> (32 - r));
}

// Bit-exact replica of jax.random.uniform(jax.random.key(42), (B,1,P,32)) with
// the PARTITIONABLE threefry implementation (default in modern JAX):
//   per element, 64-bit counter = row-major flat index f;
//   threefry2x32(key=[0,42], x0 = hi32(f) = 0, x1 = lo32(f) = f);
//   32-bit draw = x0_final ^ x1_final;
//   u = bitcast((bits >> 9) | 0x3f800000) - 1;  angle = (u - 0.5) * 2*pi.
__device__ __forceinline__ float rand_angle(uint32_t f) {
    const uint32_t k0 = 0u, k1 = 42u;
    const uint32_t k2 = 0x1BD11BDAu ^ k0 ^ k1;
    uint32_t x0 = 0u + k0;   // hi half of the 64-bit counter (always 0 here)
    uint32_t x1 = f + k1;    // lo half
#define R4(a, b, c, d)                         \
    x0 += x1; x1 = rotl32(x1, a); x1 ^= x0;    \
    x0 += x1; x1 = rotl32(x1, b); x1 ^= x0;    \
    x0 += x1; x1 = rotl32(x1, c); x1 ^= x0;    \
    x0 += x1; x1 = rotl32(x1, d); x1 ^= x0;
    R4(13, 15, 26, 6)   x0 += k1; x1 += k2 + 1u;
    R4(17, 29, 16, 24)  x0 += k2; x1 += k0 + 2u;
    R4(13, 15, 26, 6)   x0 += k0; x1 += k1 + 3u;
    R4(17, 29, 16, 24)  x0 += k1; x1 += k2 + 4u;
    R4(13, 15, 26, 6)   x0 += k2; x1 += k0 + 5u;
#undef R4
    uint32_t bits = x0 ^ x1;   // 32-bit fold used by partitionable threefry
    float u = __fsub_rn(__uint_as_float((bits >> 9) | 0x3F800000u), 1.0f);
    return __fmul_rn(__fsub_rn(u, 0.5f), 6.28318530717958647692f);
}

// One warp per query point.
__global__ void __launch_bounds__(256, 4)
qgq_kernel(const float* __restrict__ new_xyz,   // (B, P, 3)
           float* __restrict__ out)             // (B, 34, P, 32)
{
    const int wglobal = (blockIdx.x * blockDim.x + threadIdx.x) >> 5;
    const int lane    = threadIdx.x & 31;
    if (wglobal >= Bc * Pc) return;
    const int b = wglobal / Pc;
    const int p = wglobal % Pc;

    __shared__ int s_idx[8][32];
    int* slots = s_idx[threadIdx.x >> 5];

    const float* c3 = new_xyz + (size_t)(b * Pc + p) * 3;
    const float cx = c3[0], cy = c3[1], cz = c3[2];
    const float4* pts = g_xyz4 + (size_t)b * Nc;

    // ---- ball query: first 32 ascending-index hits, early exit ----
    int cnt = 0;
    const unsigned lt_mask = (1u << lane) - 1u;
    for (int base = 0; base < Nc; base += 32) {
        float4 q = pts[base + lane];
        float dx = __fsub_rn(cx, q.x);
        float dy = __fsub_rn(cy, q.y);
        float dz = __fsub_rn(cz, q.z);
        float d2 = d3(dx, dy, dz, dx, dy, dz);
        bool hit = d2 < 0.04f;                 // RADIUS^2 in f32
        unsigned m = __ballot_sync(FULLMASK, hit);
        if (hit) {
            int slot = cnt + __popc(m & lt_mask);
            if (slot < 32) slots[slot] = base + lane;
        }
        cnt += __popc(m);
        if (cnt >= 32) break;
    }
    __syncwarp();
    if (lane >= cnt) slots[lane] = slots[0];   // pad with first hit (cnt >= 1 always)
    __syncwarp();
    const int myn = slots[lane];

    // ---- relative vector ----
    float4 q4 = pts[myn];
    float vx = __fsub_rn(q4.x, cx);
    float vy = __fsub_rn(q4.y, cy);
    float vz = __fsub_rn(q4.z, cz);

    // ---- p1 = normalize(center); p2 = normalize(p1) (double-normalized in ref) ----
    const float eps = 1e-6f;
    float cn  = sqrtf(d3(cx, cy, cz, cx, cy, cz));
    float cd  = __fadd_rn(cn, eps);
    float p1x = __fdiv_rn(cx, cd), p1y = __fdiv_rn(cy, cd), p1z = __fdiv_rn(cz, cd);

    float n1  = sqrtf(d3(p1x, p1y, p1z, p1x, p1y, p1z));
    float n1d = __fadd_rn(n1, eps);
    float p2x = __fdiv_rn(p1x, n1d), p2y = __fdiv_rn(p1y, n1d), p2z = __fdiv_rn(p1z, n1d);

    // ---- ref = _project_one(p1) ----
    bool colin = fabsf(p2x) > 0.999f;
    float rx, ry, rz;
    if (colin) {
        rx = -__fmul_rn(p2y, p2x);
        ry = __fsub_rn(1.0f, __fmul_rn(p2y, p2y));
        rz = -__fmul_rn(p2y, p2z);
    } else {
        rx = __fsub_rn(1.0f, __fmul_rn(p2x, p2x));
        ry = -__fmul_rn(p2x, p2y);
        rz = -__fmul_rn(p2x, p2z);
    }
    float rn_  = sqrtf(d3(rx, ry, rz, rx, ry, rz));
    float rnd_ = __fadd_rn(rn_, eps);
    float rfx = __fdiv_rn(rx, rnd_), rfy = __fdiv_rn(ry, rnd_), rfz = __fdiv_rn(rz, rnd_);

    // ---- projection onto plane perpendicular to p1 ----
    float dotpv = d3(p1x, p1y, p1z, vx, vy, vz);
    float ddx = __fsub_rn(vx, __fmul_rn(dotpv, p1x));
    float ddy = __fsub_rn(vy, __fmul_rn(dotpv, p1y));
    float ddz = __fsub_rn(vz, __fmul_rn(dotpv, p1z));
    float pn  = sqrtf(d3(ddx, ddy, ddz, ddx, ddy, ddz));
    float pnd = __fadd_rn(pn, eps);
    float pjx = __fdiv_rn(ddx, pnd), pjy = __fdiv_rn(ddy, pnd), pjz = __fdiv_rn(ddz, pnd);

    // ---- angle = atan2(triple(ref,proj,p1), ref.proj), random if degenerate ----
    float cxp = __fsub_rn(__fmul_rn(rfy, pjz), __fmul_rn(rfz, pjy));
    float cyp = __fsub_rn(__fmul_rn(rfz, pjx), __fmul_rn(rfx, pjz));
    float czp = __fsub_rn(__fmul_rn(rfx, pjy), __fmul_rn(rfy, pjx));
    float sinus   = d3(cxp, cyp, czp, p1x, p1y, p1z);
    float cosinus = d3(rfx, rfy, rfz, pjx, pjy, pjz);
    float pn2 = d3(pjx, pjy, pjz, pjx, pjy, pjz);

    float angle;
    if (pn2 < 1e-12f) {
        uint32_t flat = (uint32_t)((b * Pc + p) * Sc + lane);
        angle = rand_angle(flat);
    } else {
        angle = atan2f(sinus, cosinus);   // XLA atan2 lowers to __nv_atan2f: identical
    }

    // ---- stable argsort via warp bitonic on (ordered-float(angle), lane) ----
    unsigned ab = __float_as_uint(angle);
    ab = (ab & 0x80000000u) ? ~ab : (ab | 0x80000000u);
    unsigned long long key = ((unsigned long long)ab << 32) | (unsigned)lane;
    #pragma unroll
    for (int k = 2; k <= 32; k <<= 1) {
        #pragma unroll
        for (int j = k >> 1; j > 0; j >>= 1) {
            unsigned long long o = __shfl_xor_sync(FULLMASK, key, j);
            bool up      = ((lane & k) == 0);
            bool lower   = ((lane & j) == 0);
            bool takeMin = (up == lower);
            key = ((key < o) == takeMin) ? key : o;
        }
    }
    int src = (int)(key & 31u);
    float svx = __shfl_sync(FULLMASK, vx, src);
    float svy = __shfl_sync(FULLMASK, vy, src);
    float svz = __shfl_sync(FULLMASK, vz, src);

    // ---- invariance features ----
    float ss   = d3(svx, svy, svz, svx, svy, svz);
    float n2   = sqrtf(__fadd_rn(ss, 1e-12f));
    float cang = __fdiv_rn(d3(p1x, p1y, p1z, svx, svy, svz), n2);
    cang = fminf(fmaxf(cang, -0.999999f), 0.999999f);
    float iang = acosf(cang);

    // ---- quaternion ----
    float dist = sqrtf(ss);
    float od   = __fadd_rn(dist, eps);
    float ox = __fdiv_rn(svx, od), oy = __fdiv_rn(svy, od), oz = __fdiv_rn(svz, od);
    float theta = __fmul_rn(__fdiv_rn(dist, 0.2f), 1.57079632679489661923f);
    float qw = cosf(theta);
    float sn = sinf(theta);
    float qx = __fmul_rn(sn, ox);
    float qy = __fmul_rn(sn, oy);
    float qz = __fmul_rn(sn, oz);

    // ---- write output: out[b][ch][p][s], ch: 0=norm,1=angle, 2+qi*8+m = roll(q_qi,-m) ----
    float* ob = out + (((size_t)b * 34) * Pc + p) * Sc + lane;
    const size_t chs = (size_t)Pc * Sc;
    ob[0 * chs] = n2;
    ob[1 * chs] = iang;

    float qv0 = qw, qv1 = qx, qv2 = qy, qv3 = qz;
    #pragma unroll
    for (int m = 0; m < 8; m++) {
        int srcl = (lane + m) & 31;
        float r0 = __shfl_sync(FULLMASK, qv0, srcl);
        float r1 = __shfl_sync(FULLMASK, qv1, srcl);
        float r2 = __shfl_sync(FULLMASK, qv2, srcl);
        float r3 = __shfl_sync(FULLMASK, qv3, srcl);
        ob[(size_t)(2 + 0 * 8 + m) * chs] = r0;
        ob[(size_t)(2 + 1 * 8 + m) * chs] = r1;
        ob[(size_t)(2 + 2 * 8 + m) * chs] = r2;
        ob[(size_t)(2 + 3 * 8 + m) * chs] = r3;
    }
}

extern "C" void kernel_launch(void* const* d_in, const int* in_sizes, int n_in,
                              void* d_out, int out_size) {
    const float* xyz     = (const float*)d_in[0];   // (4, 8192, 3)
    const float* new_xyz = (const float*)d_in[1];   // (4, 2048, 3)
    // d_in[2] = fps_idx: unused (its column is dropped by grouped[..., 1:])
    float* out = (float*)d_out;                     // (4, 34, 2048, 32)

    pack_xyz_kernel<<<(Bc * Nc + 255) / 256, 256>>>(xyz);

    // 8192 query points, one warp each: 1024 blocks x 256 threads
    qgq_kernel<<<(Bc * Pc * 32) / 256, 256>>>(new_xyz, out);
}